// round 10
// baseline (speedup 1.0000x reference)
#include <cuda_runtime.h>

#define NG      8000
#define NGATE   16000
#define NCTA    296
#define GMAX    55
#define NB      32
#define NP      64
#define NITER   50
#define NT      512
#define DTF     0.02f
#define INV_DT_SKIP 2.5f

typedef unsigned long long u64;

// ---------------- device scratch ----------------
__device__ float    g_S[4][NB*NP];        // rotating reduction buffers
__device__ float    g_invT[2][NP*NP];     // inverses, j-major: [j*64+i] = inv[i][j]
__device__ unsigned g_counter;

// ---------------- helpers ----------------
__device__ __forceinline__ u64 fma2(u64 a, u64 b, u64 c) {
    u64 d; asm("fma.rn.f32x2 %0, %1, %2, %3;" : "=l"(d) : "l"(a), "l"(b), "l"(c)); return d;
}
__device__ __forceinline__ u64 mul2(u64 a, u64 b) {
    u64 d; asm("mul.rn.f32x2 %0, %1, %2;" : "=l"(d) : "l"(a), "l"(b)); return d;
}
__device__ __forceinline__ u64 dup2(float x) {
    unsigned xi = __float_as_uint(x);
    u64 d; asm("mov.b64 %0, {%1, %2};" : "=l"(d) : "r"(xi), "r"(xi)); return d;
}
__device__ __forceinline__ void unpack2(u64 v, float& lo, float& hi) {
    unsigned a, b; asm("mov.b64 {%0, %1}, %2;" : "=r"(a), "=r"(b) : "l"(v));
    lo = __uint_as_float(a); hi = __uint_as_float(b);
}
__device__ __forceinline__ unsigned ldacq(const unsigned* p) {
    unsigned v; asm volatile("ld.acquire.gpu.u32 %0, [%1];" : "=r"(v) : "l"(p)); return v;
}
__device__ __forceinline__ unsigned atom_inc_acqrel(unsigned* p) {
    unsigned v, one = 1u;
    asm volatile("atom.add.acq_rel.gpu.u32 %0, [%1], %2;" : "=r"(v) : "l"(p), "r"(one)); return v;
}
__device__ __forceinline__ void redadd(float* p, float v) {
    asm volatile("red.add.f32 [%0], %1;" :: "l"(p), "f"(v));
}

// ---------------- init: matrix inverses + reset ----------------
__global__ void init_kernel(const float* __restrict__ Ap) {
    __shared__ float M[NP][2*NP + 1];
    __shared__ float fac[NP];
    __shared__ float s_piv;
    int t = threadIdx.x;

    for (int pass = 0; pass < 2; ++pass) {
        float dscale = (pass == 0) ? 1.0f : 3.0f;
        float ascale = (pass == 0) ? DTF : 2.0f * DTF;
        for (int idx = t; idx < NP*NP; idx += 256) {
            int i = idx >> 6, j = idx & 63;
            M[i][j]      = ((i == j) ? dscale : 0.0f) - ascale * Ap[idx];
            M[i][j + NP] = (i == j) ? 1.0f : 0.0f;
        }
        __syncthreads();
        for (int c = 0; c < NP; ++c) {
            if (t == 0) s_piv = 1.0f / M[c][c];
            __syncthreads();
            float ip = s_piv;
            if (t < 2*NP) M[c][t] *= ip;
            if (t < NP)   fac[t] = (t == c) ? 0.0f : M[t][c];
            __syncthreads();
            for (int idx = t; idx < NP * 2 * NP; idx += 256) {
                int r = idx >> 7, j = idx & 127;
                if (r != c) M[r][j] -= fac[r] * M[c][j];
            }
            __syncthreads();
        }
        for (int idx = t; idx < NP*NP; idx += 256) {
            int j = idx >> 6, i = idx & 63;
            g_invT[pass][idx] = M[i][j + NP];   // j-major
        }
        __syncthreads();
    }
    for (int idx = t; idx < 4*NB*NP; idx += 256) ((float*)g_S)[idx] = 0.0f;
    if (t == 0) g_counter = 0u;
    __threadfence();
}

// ---------------- SMEM layout (bytes) ----------------
#define SM_W     0                 // [g 55][kslot 64][c 4] f32, k XOR (g&7)  : 56320
#define SM_P     56320             // [g 55][p 64] f32 (stride 256)           : 14080
#define SM_F     70400             // [g 55] stride 144B (16 u64 b-pairs)     : 7920
#define SM_A     78320             // [k 64][bp 16] u64                       : 8192
#define SM_R     86512             // [j 64] stride 136B                      : 8704
#define SMEM_TOTAL 95216

extern __shared__ char smem_raw[];

__global__ void __launch_bounds__(NT, 2)
persist_kernel(const float* __restrict__ state,
               const float* __restrict__ Wu, const float* __restrict__ Wv,
               const float* __restrict__ Pp, float* __restrict__ out)
{
    const int t   = threadIdx.x;
    const int cta = blockIdx.x;

    const int gstart = (int)(((long)cta * 2000) / 37);
    const int gcnt   = (int)(((long)(cta + 1) * 2000) / 37) - gstart;

    // ================= one-time staging =================
    // W: [g][kslot][c], kslot = k ^ (g&7)
    for (int idx = t; idx < gcnt*4*16; idx += NT) {
        int g = idx >> 6, r = (idx >> 4) & 3, k4 = idx & 15;
        int gate = gstart + g;
        const float4* src = (const float4*)((gate < NG) ? Wu : Wv);
        int base = (gate < NG) ? gate : (gate - NG);
        float4 v = __ldg(src + (base + r*NG)*16 + k4);
        float vv[4] = {v.x, v.y, v.z, v.w};
        int xr = g & 7;
        #pragma unroll
        for (int j = 0; j < 4; ++j) {
            int k = k4*4 + j;
            *(float*)(smem_raw + SM_W + g*1024 + (k ^ xr)*16 + r*4) = vv[j];
        }
    }
    // P: [g][p] (stride 256B)
    for (int idx = t; idx < gcnt*(NP/4); idx += NT) {
        int g = idx >> 4, p4 = idx & 15;
        int gate = gstart + g;
        float pv[4];
        #pragma unroll
        for (int j = 0; j < 4; ++j)
            pv[j] = __ldg(Pp + (p4*4 + j)*NGATE + gate);
        *(float4*)(smem_raw + SM_P + g*256 + p4*16) = make_float4(pv[0], pv[1], pv[2], pv[3]);
    }
    // a: [k][bp] u64
    for (int idx = t; idx < NB*NP; idx += NT) {
        int b = idx >> 6, k = idx & 63;
        *(float*)(smem_raw + SM_A + k*128 + (b >> 1)*8 + (b & 1)*4) = state[idx];
    }

    // ---- static mappings ----
    // phase 1: thread = (gate g1, bp-pair sub)  : 8 threads/gate
    const int g1 = t >> 3, sub = t & 7;
    const bool p1v = (g1 < gcnt);
    const char* wb = smem_raw + SM_W + g1*1024;
    const unsigned xr16 = ((unsigned)(g1 & 7)) * 16u;
    const char* ab = smem_raw + SM_A + sub*16;
    // phase 2: thread = (batch b2 32, p-quad p4 16)
    const int b2 = t & 31, p4 = t >> 5;
    // matvec (256 active): thread = (b-pair bpu 16, i-quad i4 16)
    const int bpu = t & 15, i4 = (t >> 4) & 15;
    const bool mvv = (t < 256);

    float aprv[4], fprv[4];
    #pragma unroll
    for (int e = 0; e < 4; ++e) { aprv[e] = 0.0f; fprv[e] = 0.0f; }

    __syncthreads();

    for (int it = 0; it < NITER; ++it) {
        // ========== phase 1: z = a@W^T (1 gate x 4 comps x 2 bp) ==========
        if (p1v) {
            u64 acc[4][2];
            #pragma unroll
            for (int c = 0; c < 4; ++c) { acc[c][0] = 0; acc[c][1] = 0; }

            #pragma unroll 4
            for (int k = 0; k < NP; ++k) {
                float4 w = *(const float4*)(wb + (((unsigned)(k * 16)) ^ xr16));
                ulonglong2 av = *(const ulonglong2*)(ab + k*128);
                u64 d0 = dup2(w.x), d1 = dup2(w.y), d2 = dup2(w.z), d3 = dup2(w.w);
                acc[0][0] = fma2(d0, av.x, acc[0][0]); acc[0][1] = fma2(d0, av.y, acc[0][1]);
                acc[1][0] = fma2(d1, av.x, acc[1][0]); acc[1][1] = fma2(d1, av.y, acc[1][1]);
                acc[2][0] = fma2(d2, av.x, acc[2][0]); acc[2][1] = fma2(d2, av.y, acc[2][1]);
                acc[3][0] = fma2(d3, av.x, acc[3][0]); acc[3][1] = fma2(d3, av.y, acc[3][1]);
            }
            u64 f0 = fma2(acc[1][0], acc[3][0], mul2(acc[0][0], acc[2][0]));
            u64 f1 = fma2(acc[1][1], acc[3][1], mul2(acc[0][1], acc[2][1]));
            *(ulonglong2*)(smem_raw + SM_F + g1*144 + sub*16) = make_ulonglong2(f0, f1);
        }
        __syncthreads();

        // ========== phase 2: S[b][4p] = sum_g f[g][b] * P[g][4p]  (all gates) ==========
        {
            float q0 = 0.0f, q1 = 0.0f, q2 = 0.0f, q3 = 0.0f;
            const char* fb = smem_raw + SM_F + (b2 >> 1)*8 + (b2 & 1)*4;
            const char* pb = smem_raw + SM_P + p4*16;
            #pragma unroll 4
            for (int g = 0; g < gcnt; ++g) {
                float fs = *(const float*)(fb + g*144);
                float4 pv = *(const float4*)(pb + g*256);
                q0 = fmaf(fs, pv.x, q0);
                q1 = fmaf(fs, pv.y, q1);
                q2 = fmaf(fs, pv.z, q2);
                q3 = fmaf(fs, pv.w, q3);
            }
            float* Sb = g_S[it & 3] + b2*NP + p4*4;
            redadd(Sb    , q0);
            redadd(Sb + 1, q1);
            redadd(Sb + 2, q2);
            redadd(Sb + 3, q3);
        }

        // ========== single global barrier ==========
        __threadfence();
        __syncthreads();
        if (t == 0) atom_inc_acqrel(&g_counter);
        if (it == NITER - 1 && cta != 0) return;
        if (t == 0) {
            const unsigned tgt = (unsigned)NCTA * (unsigned)(it + 1);
            while (ldacq(&g_counter) < tgt) { }
        }
        __syncthreads();

        // zero buffer used 1 iter ago (rewritten at it+3; ordered by barrier chain)
        if (t < 7) {
            int z = cta*7 + t;
            if (z < NB*NP) __stcg(&g_S[(it + 3) & 3][z], 0.0f);
        }

        // ========== update step 1: r ==========
        {
            const float* Sb = g_S[it & 3];
            #pragma unroll
            for (int e = 0; e < 4; ++e) {
                int idx = t + e*NT;
                int b = idx >> 6, j = idx & 63;
                float f  = -__ldcv(Sb + idx);
                float av = *(const float*)(smem_raw + SM_A + j*128 + (b >> 1)*8 + (b & 1)*4);
                float r;
                if (it == 0) r = av + DTF * f;
                else         r = 4.0f*av - aprv[e] + 4.0f*DTF*f - 2.0f*DTF*fprv[e];
                aprv[e] = av; fprv[e] = f;
                *(float*)(smem_raw + SM_R + j*136 + (b >> 1)*8 + (b & 1)*4) = r;
            }
        }
        __syncthreads();

        // ========== update step 2: a_next = inv @ r (256 threads; inv via L1) ==========
        if (mvv) {
            const float* invg = g_invT[(it == 0) ? 0 : 1];
            u64 m[4] = {0, 0, 0, 0};
            const char* rb = smem_raw + SM_R + bpu*8;
            #pragma unroll 4
            for (int j = 0; j < NP; ++j) {
                u64 rv = *(const u64*)(rb + j*136);
                float4 iv = __ldg((const float4*)(invg + j*64 + i4*4));
                m[0] = fma2(rv, dup2(iv.x), m[0]);
                m[1] = fma2(rv, dup2(iv.y), m[1]);
                m[2] = fma2(rv, dup2(iv.z), m[2]);
                m[3] = fma2(rv, dup2(iv.w), m[3]);
            }
            if (it < NITER - 1) {
                #pragma unroll
                for (int qq = 0; qq < 4; ++qq)
                    *(u64*)(smem_raw + SM_A + (i4*4 + qq)*128 + bpu*8) = m[qq];
            } else {   // only CTA0 reaches here
                #pragma unroll
                for (int qq = 0; qq < 4; ++qq) {
                    int i = i4*4 + qq;
                    float lo, hi; unpack2(m[qq], lo, hi);
                    out[(2*bpu    )*NP + i] = (lo - __ldg(&state[(2*bpu    )*NP + i])) * INV_DT_SKIP;
                    out[(2*bpu + 1)*NP + i] = (hi - __ldg(&state[(2*bpu + 1)*NP + i])) * INV_DT_SKIP;
                }
            }
        }
        __syncthreads();
    }
}

// ---------------- launcher ----------------
extern "C" void kernel_launch(void* const* d_in, const int* in_sizes, int n_in,
                              void* d_out, int out_size) {
    const float* state = (const float*)d_in[0];
    const float* Ap    = (const float*)d_in[1];
    const float* Wu    = (const float*)d_in[2];
    const float* Wv    = (const float*)d_in[3];
    const float* Pp    = (const float*)d_in[4];
    float* out = (float*)d_out;
    (void)in_sizes; (void)n_in; (void)out_size;

    cudaFuncSetAttribute(persist_kernel,
                         cudaFuncAttributeMaxDynamicSharedMemorySize, SMEM_TOTAL);

    init_kernel<<<1, 256>>>(Ap);
    persist_kernel<<<NCTA, NT, SMEM_TOTAL>>>(state, Wu, Wv, Pp, out);
}

// round 11
// speedup vs baseline: 1.2369x; 1.2369x over previous
#include <cuda_runtime.h>

#define NG      8000
#define NGATE   16000
#define NCTA    125
#define GPC     128
#define NB      32
#define NP      64
#define NITER   50
#define NT      512
#define DTF     0.02f
#define INV_DT_SKIP 2.5f

typedef unsigned long long u64;

// ---------------- device scratch ----------------
__device__ float    g_S[4][NB*NP];        // rotating reduction buffers
__device__ float    g_invT[2][NP*NP];     // inverses, j-major: [j*64+i] = inv[i][j]
__device__ unsigned g_counter;

// ---------------- helpers ----------------
__device__ __forceinline__ u64 fma2(u64 a, u64 b, u64 c) {
    u64 d; asm("fma.rn.f32x2 %0, %1, %2, %3;" : "=l"(d) : "l"(a), "l"(b), "l"(c)); return d;
}
__device__ __forceinline__ u64 mul2(u64 a, u64 b) {
    u64 d; asm("mul.rn.f32x2 %0, %1, %2;" : "=l"(d) : "l"(a), "l"(b)); return d;
}
__device__ __forceinline__ u64 dup2(float x) {
    unsigned xi = __float_as_uint(x);
    u64 d; asm("mov.b64 %0, {%1, %2};" : "=l"(d) : "r"(xi), "r"(xi)); return d;
}
__device__ __forceinline__ void unpack2(u64 v, float& lo, float& hi) {
    unsigned a, b; asm("mov.b64 {%0, %1}, %2;" : "=r"(a), "=r"(b) : "l"(v));
    lo = __uint_as_float(a); hi = __uint_as_float(b);
}
__device__ __forceinline__ unsigned ldacq(const unsigned* p) {
    unsigned v; asm volatile("ld.acquire.gpu.u32 %0, [%1];" : "=r"(v) : "l"(p)); return v;
}
__device__ __forceinline__ unsigned atom_inc_acqrel(unsigned* p) {
    unsigned v, one = 1u;
    asm volatile("atom.add.acq_rel.gpu.u32 %0, [%1], %2;" : "=r"(v) : "l"(p), "r"(one)); return v;
}
__device__ __forceinline__ void redadd(float* p, float v) {
    asm volatile("red.add.f32 [%0], %1;" :: "l"(p), "f"(v));
}

// ---------------- init: matrix inverses + reset ----------------
__global__ void init_kernel(const float* __restrict__ Ap) {
    __shared__ float M[NP][2*NP + 1];
    __shared__ float fac[NP];
    __shared__ float s_piv;
    int t = threadIdx.x;

    for (int pass = 0; pass < 2; ++pass) {
        float dscale = (pass == 0) ? 1.0f : 3.0f;
        float ascale = (pass == 0) ? DTF : 2.0f * DTF;
        for (int idx = t; idx < NP*NP; idx += 256) {
            int i = idx >> 6, j = idx & 63;
            M[i][j]      = ((i == j) ? dscale : 0.0f) - ascale * Ap[idx];
            M[i][j + NP] = (i == j) ? 1.0f : 0.0f;
        }
        __syncthreads();
        for (int c = 0; c < NP; ++c) {
            if (t == 0) s_piv = 1.0f / M[c][c];
            __syncthreads();
            float ip = s_piv;
            if (t < 2*NP) M[c][t] *= ip;
            if (t < NP)   fac[t] = (t == c) ? 0.0f : M[t][c];
            __syncthreads();
            for (int idx = t; idx < NP * 2 * NP; idx += 256) {
                int r = idx >> 7, j = idx & 127;
                if (r != c) M[r][j] -= fac[r] * M[c][j];
            }
            __syncthreads();
        }
        for (int idx = t; idx < NP*NP; idx += 256) {
            int j = idx >> 6, i = idx & 63;
            g_invT[pass][idx] = M[i][j + NP];   // j-major
        }
        __syncthreads();
    }
    for (int idx = t; idx < 4*NB*NP; idx += 256) ((float*)g_S)[idx] = 0.0f;
    if (t == 0) g_counter = 0u;
    __threadfence();
}

// ---------------- SMEM layout (bytes) ----------------
#define SM_W     0                 // [g 128][kslot 64][c 4] f32, k XOR (g&7) : 131072
#define SM_P     131072            // [g 128][p 64] f32 (stride 256)          : 32768
#define SM_F     163840            // [g 128] stride 144B (16 u64 b-pairs)    : 18432
#define SM_A     182272            // [k 64][bp 16] u64                       : 8192
#define SM_R     190464            // [j 64] stride 136B                      : 8704
#define SMEM_TOTAL 199168

extern __shared__ char smem_raw[];

__global__ void __launch_bounds__(NT, 1)
persist_kernel(const float* __restrict__ state,
               const float* __restrict__ Wu, const float* __restrict__ Wv,
               const float* __restrict__ Pp, float* __restrict__ out)
{
    const int t   = threadIdx.x;
    const int cta = blockIdx.x;

    // ================= one-time staging =================
    // W: [g][kslot][c], kslot = k ^ (g&7)
    for (int idx = t; idx < GPC*4*16; idx += NT) {
        int g = idx >> 6, r = (idx >> 4) & 3, k4 = idx & 15;
        int gate = cta * GPC + g;
        const float4* src = (const float4*)((gate < NG) ? Wu : Wv);
        int base = (gate < NG) ? gate : (gate - NG);
        float4 v = __ldg(src + (base + r*NG)*16 + k4);
        float vv[4] = {v.x, v.y, v.z, v.w};
        int xr = g & 7;
        #pragma unroll
        for (int j = 0; j < 4; ++j) {
            int k = k4*4 + j;
            *(float*)(smem_raw + SM_W + g*1024 + (k ^ xr)*16 + r*4) = vv[j];
        }
    }
    // P: [g][p] (stride 256B)
    for (int idx = t; idx < (GPC*NP)/4; idx += NT) {
        int p = idx >> 5, g4 = idx & 31;
        float4 v = __ldg((const float4*)(Pp + p*NGATE + cta*GPC + g4*4));
        float vv[4] = {v.x, v.y, v.z, v.w};
        #pragma unroll
        for (int j = 0; j < 4; ++j)
            *(float*)(smem_raw + SM_P + (g4*4 + j)*256 + p*4) = vv[j];
    }
    // a: [k][bp] u64
    for (int idx = t; idx < NB*NP; idx += NT) {
        int b = idx >> 6, k = idx & 63;
        *(float*)(smem_raw + SM_A + k*128 + (b >> 1)*8 + (b & 1)*4) = state[idx];
    }

    // ---- static mappings ----
    // phase 1: thread = (gate g1 128, batch-quarter bq 4)
    const int g1 = t >> 2, bq = t & 3;
    const char* wb = smem_raw + SM_W + g1*1024;
    const unsigned xr16 = ((unsigned)(g1 & 7)) * 16u;
    const char* ab = smem_raw + SM_A + bq*32;
    // phase 2: thread = (batch b2 32, p-quad p4 16)
    const int b2 = t & 31, p4 = t >> 5;
    // matvec: thread = (b-pair bpu 16, i-pair ip 32)
    const int bpu = t & 15, ip = t >> 4;

    float aprv[4], fprv[4];
    #pragma unroll
    for (int e = 0; e < 4; ++e) { aprv[e] = 0.0f; fprv[e] = 0.0f; }

    __syncthreads();

    for (int it = 0; it < NITER; ++it) {
        // ========== phase 1: z = a@W^T (1 gate x 4 comps x 4 bp) ==========
        {
            u64 acc[4][4];
            #pragma unroll
            for (int c = 0; c < 4; ++c)
                #pragma unroll
                for (int i = 0; i < 4; ++i) acc[c][i] = 0;

            #pragma unroll 8
            for (int k = 0; k < NP; ++k) {
                float4 w = *(const float4*)(wb + (((unsigned)(k * 16)) ^ xr16));
                ulonglong2 aA = *(const ulonglong2*)(ab + k*128);
                ulonglong2 aB = *(const ulonglong2*)(ab + k*128 + 16);
                u64 av[4] = {aA.x, aA.y, aB.x, aB.y};
                u64 d[4] = {dup2(w.x), dup2(w.y), dup2(w.z), dup2(w.w)};
                #pragma unroll
                for (int c = 0; c < 4; ++c)
                    #pragma unroll
                    for (int i = 0; i < 4; ++i)
                        acc[c][i] = fma2(d[c], av[i], acc[c][i]);
            }
            // f = u*dx + v*dy
            u64 f0 = fma2(acc[1][0], acc[3][0], mul2(acc[0][0], acc[2][0]));
            u64 f1 = fma2(acc[1][1], acc[3][1], mul2(acc[0][1], acc[2][1]));
            u64 f2 = fma2(acc[1][2], acc[3][2], mul2(acc[0][2], acc[2][2]));
            u64 f3 = fma2(acc[1][3], acc[3][3], mul2(acc[0][3], acc[2][3]));
            char* fb = smem_raw + SM_F + g1*144 + bq*32;
            *(ulonglong2*)(fb)      = make_ulonglong2(f0, f1);
            *(ulonglong2*)(fb + 16) = make_ulonglong2(f2, f3);
        }
        __syncthreads();

        // ========== phase 2: S[b][4p] = sum_g f[g][b] * P[g][4p] ==========
        {
            float q0 = 0.0f, q1 = 0.0f, q2 = 0.0f, q3 = 0.0f;
            const char* fb = smem_raw + SM_F + (b2 >> 1)*8 + (b2 & 1)*4;
            const char* pb = smem_raw + SM_P + p4*16;
            #pragma unroll 8
            for (int g = 0; g < GPC; ++g) {
                float fs = *(const float*)(fb + g*144);
                float4 pv = *(const float4*)(pb + g*256);
                q0 = fmaf(fs, pv.x, q0);
                q1 = fmaf(fs, pv.y, q1);
                q2 = fmaf(fs, pv.z, q2);
                q3 = fmaf(fs, pv.w, q3);
            }
            float* Sb = g_S[it & 3] + b2*NP + p4*4;
            redadd(Sb    , q0);
            redadd(Sb + 1, q1);
            redadd(Sb + 2, q2);
            redadd(Sb + 3, q3);
        }

        // ========== single global barrier ==========
        __threadfence();
        __syncthreads();
        if (t == 0) atom_inc_acqrel(&g_counter);
        if (it == NITER - 1 && cta != 0) return;
        if (t == 0) {
            const unsigned tgt = (unsigned)NCTA * (unsigned)(it + 1);
            while (ldacq(&g_counter) < tgt) { }
        }
        __syncthreads();

        // zero buffer used 1 iter ago (rewritten at it+3; ordered by barrier chain)
        if (t < 17) {
            int z = cta*17 + t;
            if (z < NB*NP) __stcg(&g_S[(it + 3) & 3][z], 0.0f);
        }

        // ========== update step 1: r ==========
        {
            const float* Sb = g_S[it & 3];
            #pragma unroll
            for (int e = 0; e < 4; ++e) {
                int idx = t + e*NT;
                int b = idx >> 6, j = idx & 63;
                float f  = -__ldcv(Sb + idx);
                float av = *(const float*)(smem_raw + SM_A + j*128 + (b >> 1)*8 + (b & 1)*4);
                float r;
                if (it == 0) r = av + DTF * f;
                else         r = 4.0f*av - aprv[e] + 4.0f*DTF*f - 2.0f*DTF*fprv[e];
                aprv[e] = av; fprv[e] = f;
                *(float*)(smem_raw + SM_R + j*136 + (b >> 1)*8 + (b & 1)*4) = r;
            }
        }
        __syncthreads();

        // ========== update step 2: a_next = inv @ r (all 512; inv via L1) ==========
        {
            const float* invg = g_invT[(it == 0) ? 0 : 1];
            u64 m0 = 0, m1 = 0;
            const char* rb = smem_raw + SM_R + bpu*8;
            const int i = ip*2;
            #pragma unroll 8
            for (int j = 0; j < NP; ++j) {
                u64 rv = *(const u64*)(rb + j*136);
                float2 iv = __ldg((const float2*)(invg + j*64 + i));
                m0 = fma2(rv, dup2(iv.x), m0);
                m1 = fma2(rv, dup2(iv.y), m1);
            }
            if (it < NITER - 1) {
                *(u64*)(smem_raw + SM_A + (i    )*128 + bpu*8) = m0;
                *(u64*)(smem_raw + SM_A + (i + 1)*128 + bpu*8) = m1;
            } else {   // only CTA0 reaches here
                float l0, h0, l1, h1;
                unpack2(m0, l0, h0); unpack2(m1, l1, h1);
                out[(2*bpu    )*NP + i    ] = (l0 - __ldg(&state[(2*bpu    )*NP + i    ])) * INV_DT_SKIP;
                out[(2*bpu + 1)*NP + i    ] = (h0 - __ldg(&state[(2*bpu + 1)*NP + i    ])) * INV_DT_SKIP;
                out[(2*bpu    )*NP + i + 1] = (l1 - __ldg(&state[(2*bpu    )*NP + i + 1])) * INV_DT_SKIP;
                out[(2*bpu + 1)*NP + i + 1] = (h1 - __ldg(&state[(2*bpu + 1)*NP + i + 1])) * INV_DT_SKIP;
            }
        }
        __syncthreads();
    }
}

// ---------------- launcher ----------------
extern "C" void kernel_launch(void* const* d_in, const int* in_sizes, int n_in,
                              void* d_out, int out_size) {
    const float* state = (const float*)d_in[0];
    const float* Ap    = (const float*)d_in[1];
    const float* Wu    = (const float*)d_in[2];
    const float* Wv    = (const float*)d_in[3];
    const float* Pp    = (const float*)d_in[4];
    float* out = (float*)d_out;
    (void)in_sizes; (void)n_in; (void)out_size;

    cudaFuncSetAttribute(persist_kernel,
                         cudaFuncAttributeMaxDynamicSharedMemorySize, SMEM_TOTAL);

    init_kernel<<<1, 256>>>(Ap);
    persist_kernel<<<NCTA, NT, SMEM_TOTAL>>>(state, Wu, Wv, Pp, out);
}

// round 13
// speedup vs baseline: 2.2067x; 1.7841x over previous
#include <cuda_runtime.h>

#define NG      8000
#define NGATE   16000
#define NCTA    125
#define GPC     128
#define NGP     64       // gate-pairs per CTA
#define NB      32
#define NP      64
#define NITER   50
#define NT      256
#define DTF     0.02f
#define INV_DT_SKIP 2.5f

#define FSTRIDE 272      // 17*16: 16-B aligned, odd-16 for bank spread

typedef unsigned long long u64;

// ---------------- device scratch ----------------
__device__ float    g_S[4][NP*NB];        // rotating buffers, TRANSPOSED: S[p][b]
__device__ u64      g_invdup[2][NP*NP];   // inverses, j-major, value-duplicated u64
__device__ unsigned g_counter;

// ---------------- helpers ----------------
__device__ __forceinline__ u64 fma2(u64 a, u64 b, u64 c) {
    u64 d; asm("fma.rn.f32x2 %0, %1, %2, %3;" : "=l"(d) : "l"(a), "l"(b), "l"(c)); return d;
}
__device__ __forceinline__ u64 mul2(u64 a, u64 b) {
    u64 d; asm("mul.rn.f32x2 %0, %1, %2;" : "=l"(d) : "l"(a), "l"(b)); return d;
}
__device__ __forceinline__ u64 dup2(float x) {
    unsigned xi = __float_as_uint(x);
    u64 d; asm("mov.b64 %0, {%1, %2};" : "=l"(d) : "r"(xi), "r"(xi)); return d;
}
__device__ __forceinline__ void unpack2(u64 v, float& lo, float& hi) {
    unsigned a, b; asm("mov.b64 {%0, %1}, %2;" : "=r"(a), "=r"(b) : "l"(v));
    lo = __uint_as_float(a); hi = __uint_as_float(b);
}
__device__ __forceinline__ unsigned ldacq(const unsigned* p) {
    unsigned v; asm volatile("ld.acquire.gpu.u32 %0, [%1];" : "=r"(v) : "l"(p)); return v;
}
__device__ __forceinline__ unsigned atom_inc_acqrel(unsigned* p) {
    unsigned v, one = 1u;
    asm volatile("atom.add.acq_rel.gpu.u32 %0, [%1], %2;" : "=r"(v) : "l"(p), "r"(one)); return v;
}
__device__ __forceinline__ void redadd(float* p, float v) {
    asm volatile("red.add.f32 [%0], %1;" :: "l"(p), "f"(v));
}

// ---------------- init: matrix inverses (dup'd) + reset ----------------
__global__ void init_kernel(const float* __restrict__ Ap) {
    __shared__ float M[NP][2*NP + 1];
    __shared__ float fac[NP];
    __shared__ float s_piv;
    int t = threadIdx.x;

    for (int pass = 0; pass < 2; ++pass) {
        float dscale = (pass == 0) ? 1.0f : 3.0f;
        float ascale = (pass == 0) ? DTF : 2.0f * DTF;
        for (int idx = t; idx < NP*NP; idx += 256) {
            int i = idx >> 6, j = idx & 63;
            M[i][j]      = ((i == j) ? dscale : 0.0f) - ascale * Ap[idx];
            M[i][j + NP] = (i == j) ? 1.0f : 0.0f;
        }
        __syncthreads();
        for (int c = 0; c < NP; ++c) {
            if (t == 0) s_piv = 1.0f / M[c][c];
            __syncthreads();
            float ip = s_piv;
            if (t < 2*NP) M[c][t] *= ip;
            if (t < NP)   fac[t] = (t == c) ? 0.0f : M[t][c];
            __syncthreads();
            for (int idx = t; idx < NP * 2 * NP; idx += 256) {
                int r = idx >> 7, j = idx & 127;
                if (r != c) M[r][j] -= fac[r] * M[c][j];
            }
            __syncthreads();
        }
        for (int idx = t; idx < NP*NP; idx += 256) {
            int j = idx >> 6, i = idx & 63;
            g_invdup[pass][idx] = dup2(M[i][j + NP]);   // [j][i] dup'd
        }
        __syncthreads();
    }
    for (int idx = t; idx < 4*NP*NB; idx += 256) ((float*)g_S)[idx] = 0.0f;
    if (t == 0) g_counter = 0u;
    __threadfence();
}

// ---------------- SMEM layout (bytes) ----------------
#define SM_W2    0                 // [k 64][gp 64][c 4 as 2x u64, swizzled] : 131072
#define SM_P2    131072            // [gp 64][p 64] u64 gate-paired          : 32768
#define SM_F     163840            // [gp 64] stride 272B: [b 32] u64        : 17408
#define SM_AD    181248            // [k 64][b 32] u64, value-dup'd          : 16384
#define SM_R     197632            // [j 64] stride 136B: [bp 16] u64        : 8704
#define SMEM_TOTAL 206336

extern __shared__ char smem_raw[];

__global__ void __launch_bounds__(NT)
persist_kernel(const float* __restrict__ state,
               const float* __restrict__ Wu, const float* __restrict__ Wv,
               const float* __restrict__ Pp, float* __restrict__ out)
{
    const int t   = threadIdx.x;
    const int cta = blockIdx.x;

    // ================= one-time staging =================
    // W2: [k][gp][c], c01 block at +sw, c23 block at +(sw^16), sw = (gp&4)*4 (bank spread)
    for (int idx = t; idx < GPC*4*16; idx += NT) {
        int g = idx >> 6, c = (idx >> 4) & 3, k4 = idx & 15;
        int gate = cta * GPC + g;
        const float4* src = (const float4*)((gate < NG) ? Wu : Wv);
        int base = (gate < NG) ? gate : (gate - NG);
        float4 v = __ldg(src + (base + c*NG)*16 + k4);
        float vv[4] = {v.x, v.y, v.z, v.w};
        int gp = g >> 1, ge = g & 1;
        int sw = (gp & 4) * 4;
        int base16 = (c >> 1) ? (sw ^ 16) : sw;
        int off = gp*32 + base16 + (c & 1)*8 + ge*4;
        #pragma unroll
        for (int j = 0; j < 4; ++j) {
            int k = k4*4 + j;
            *(float*)(smem_raw + SM_W2 + k*2048 + off) = vv[j];
        }
    }
    // P2: [gp][p] u64 = (Pp[p][g0], Pp[p][g1])
    for (int idx = t; idx < NGP*NP; idx += NT) {
        int gp = idx & 63, p = idx >> 6;
        float2 v = __ldg((const float2*)(Pp + p*NGATE + cta*GPC + gp*2));
        *(float2*)(smem_raw + SM_P2 + gp*512 + p*8) = v;
    }
    // a_dup from state
    for (int idx = t; idx < NB*NP; idx += NT) {
        int b = idx >> 6, k = idx & 63;
        *(u64*)(smem_raw + SM_AD + k*256 + b*8) = dup2(state[idx]);
    }

    // ---- static mappings ----
    // phase 1: thread = (gate-pair gp1 64, batch-eighth bq 4)
    const int gp1 = t >> 2, bq = t & 3;
    const int swp = (gp1 & 4) * 4;
    const int wAoff = gp1*32 + swp;
    const int wBoff = gp1*32 + (swp ^ 16);
    // phase 2: thread = (batch b2 32, p-octet p8 8)
    const int b2 = t & 31, p8 = t >> 5;
    // matvec: thread = (b-pair bpu 16, i-quad ipr 16)
    const int bpu = t & 15, ipr = t >> 4;

    float aprv[8], fprv[8];
    #pragma unroll
    for (int e = 0; e < 8; ++e) { aprv[e] = 0.0f; fprv[e] = 0.0f; }

    __syncthreads();

    for (int it = 0; it < NITER; ++it) {
        // ========== phase 1: z = a@W^T (gate-paired, 4c x 8b) ==========
        {
            u64 acc[4][8];
            #pragma unroll
            for (int c = 0; c < 4; ++c)
                #pragma unroll
                for (int i = 0; i < 8; ++i) acc[c][i] = 0;

            #pragma unroll 4
            for (int k = 0; k < NP; ++k) {
                const char* row = smem_raw + SM_W2 + k*2048;
                ulonglong2 w01 = *(const ulonglong2*)(row + wAoff);
                ulonglong2 w23 = *(const ulonglong2*)(row + wBoff);
                const char* arow = smem_raw + SM_AD + k*256 + bq*64;
                ulonglong2 a0 = *(const ulonglong2*)(arow);
                ulonglong2 a1 = *(const ulonglong2*)(arow + 16);
                ulonglong2 a2 = *(const ulonglong2*)(arow + 32);
                ulonglong2 a3 = *(const ulonglong2*)(arow + 48);
                u64 av[8] = {a0.x, a0.y, a1.x, a1.y, a2.x, a2.y, a3.x, a3.y};
                #pragma unroll
                for (int i = 0; i < 8; ++i) {
                    acc[0][i] = fma2(w01.x, av[i], acc[0][i]);
                    acc[1][i] = fma2(w01.y, av[i], acc[1][i]);
                    acc[2][i] = fma2(w23.x, av[i], acc[2][i]);
                    acc[3][i] = fma2(w23.y, av[i], acc[3][i]);
                }
            }
            // f = u*dx + v*dy (still gate-paired), store [gp][b]
            char* fb = smem_raw + SM_F + gp1*FSTRIDE + bq*64;
            #pragma unroll
            for (int i2 = 0; i2 < 4; ++i2) {
                u64 fA = fma2(acc[1][2*i2    ], acc[3][2*i2    ], mul2(acc[0][2*i2    ], acc[2][2*i2    ]));
                u64 fB = fma2(acc[1][2*i2 + 1], acc[3][2*i2 + 1], mul2(acc[0][2*i2 + 1], acc[2][2*i2 + 1]));
                *(ulonglong2*)(fb + i2*16) = make_ulonglong2(fA, fB);
            }
        }
        __syncthreads();

        // ========== phase 2: S[p][b] += sum_gp f2[gp][b] .* P2[gp][p] ==========
        {
            u64 q[8];
            #pragma unroll
            for (int i = 0; i < 8; ++i) q[i] = 0;
            const char* fb2 = smem_raw + SM_F + b2*8;
            const char* pb  = smem_raw + SM_P2 + p8*64;
            #pragma unroll 4
            for (int gp = 0; gp < NGP; ++gp) {
                u64 fv = *(const u64*)(fb2 + gp*FSTRIDE);
                ulonglong2 P0 = *(const ulonglong2*)(pb + gp*512);
                ulonglong2 P1 = *(const ulonglong2*)(pb + gp*512 + 16);
                ulonglong2 P2v = *(const ulonglong2*)(pb + gp*512 + 32);
                ulonglong2 P3 = *(const ulonglong2*)(pb + gp*512 + 48);
                q[0] = fma2(fv, P0.x, q[0]);  q[1] = fma2(fv, P0.y, q[1]);
                q[2] = fma2(fv, P1.x, q[2]);  q[3] = fma2(fv, P1.y, q[3]);
                q[4] = fma2(fv, P2v.x, q[4]); q[5] = fma2(fv, P2v.y, q[5]);
                q[6] = fma2(fv, P3.x, q[6]);  q[7] = fma2(fv, P3.y, q[7]);
            }
            float* Sb = g_S[it & 3];
            #pragma unroll
            for (int j = 0; j < 8; ++j) {
                int p = p8*8 + j;
                float lo, hi; unpack2(q[j], lo, hi);
                redadd(Sb + p*NB + b2, lo + hi);   // even-gates + odd-gates
            }
        }

        // ========== single global barrier ==========
        __threadfence();
        __syncthreads();
        if (t == 0) atom_inc_acqrel(&g_counter);
        if (it == NITER - 1 && cta != 0) return;
        if (t == 0) {
            const unsigned tgt = (unsigned)NCTA * (unsigned)(it + 1);
            while (ldacq(&g_counter) < tgt) { }
        }
        __syncthreads();

        // zero buffer used 1 iter ago (rewritten at it+3; ordered by barrier chain)
        if (t < 17) {
            int z = cta*17 + t;
            if (z < NP*NB) __stcg(&g_S[(it + 3) & 3][z], 0.0f);
        }

        // ========== update step 1: r  (warp = one j row, coalesced) ==========
        {
            const float* Sb = g_S[it & 3];
            #pragma unroll
            for (int e = 0; e < 8; ++e) {
                int idx = t + e*NT;
                int b = idx & 31, j = idx >> 5;
                float f  = -__ldcv(Sb + j*NB + b);
                float av = *(const float*)(smem_raw + SM_AD + j*256 + b*8);  // low half of dup
                float r;
                if (it == 0) r = av + DTF * f;
                else         r = 4.0f*av - aprv[e] + 4.0f*DTF*f - 2.0f*DTF*fprv[e];
                aprv[e] = av; fprv[e] = f;
                *(float*)(smem_raw + SM_R + j*136 + (b >> 1)*8 + (b & 1)*4) = r;
            }
        }
        __syncthreads();

        // ========== update step 2: a_next = inv @ r; write a_dup directly ==========
        {
            const u64* invd = g_invdup[(it == 0) ? 0 : 1] + ipr*4;
            u64 m[4] = {0, 0, 0, 0};
            const char* rb = smem_raw + SM_R + bpu*8;
            #pragma unroll 4
            for (int j = 0; j < NP; ++j) {
                u64 rv = *(const u64*)(rb + j*136);
                ulonglong2 iv0 = __ldg((const ulonglong2*)(invd + j*64));
                ulonglong2 iv1 = __ldg((const ulonglong2*)(invd + j*64 + 2));
                m[0] = fma2(rv, iv0.x, m[0]);
                m[1] = fma2(rv, iv0.y, m[1]);
                m[2] = fma2(rv, iv1.x, m[2]);
                m[3] = fma2(rv, iv1.y, m[3]);
            }
            if (it < NITER - 1) {
                #pragma unroll
                for (int qq = 0; qq < 4; ++qq) {
                    int i = ipr*4 + qq;
                    float lo, hi; unpack2(m[qq], lo, hi);
                    *(u64*)(smem_raw + SM_AD + i*256 + (2*bpu    )*8) = dup2(lo);
                    *(u64*)(smem_raw + SM_AD + i*256 + (2*bpu + 1)*8) = dup2(hi);
                }
            } else {   // only CTA0 reaches here
                #pragma unroll
                for (int qq = 0; qq < 4; ++qq) {
                    int i = ipr*4 + qq;
                    float lo, hi; unpack2(m[qq], lo, hi);
                    out[(2*bpu    )*NP + i] = (lo - __ldg(&state[(2*bpu    )*NP + i])) * INV_DT_SKIP;
                    out[(2*bpu + 1)*NP + i] = (hi - __ldg(&state[(2*bpu + 1)*NP + i])) * INV_DT_SKIP;
                }
            }
        }
        __syncthreads();
    }
}

// ---------------- launcher ----------------
extern "C" void kernel_launch(void* const* d_in, const int* in_sizes, int n_in,
                              void* d_out, int out_size) {
    const float* state = (const float*)d_in[0];
    const float* Ap    = (const float*)d_in[1];
    const float* Wu    = (const float*)d_in[2];
    const float* Wv    = (const float*)d_in[3];
    const float* Pp    = (const float*)d_in[4];
    float* out = (float*)d_out;
    (void)in_sizes; (void)n_in; (void)out_size;

    cudaFuncSetAttribute(persist_kernel,
                         cudaFuncAttributeMaxDynamicSharedMemorySize, SMEM_TOTAL);

    init_kernel<<<1, 256>>>(Ap);
    persist_kernel<<<NCTA, NT, SMEM_TOTAL>>>(state, Wu, Wv, Pp, out);
}